// round 2
// baseline (speedup 1.0000x reference)
#include <cuda_runtime.h>
#include <math.h>

#define BATCH 16
#define CIN 512
#define COUT 512
#define HH 32
#define WDIM 512

// Scratch (no allocations allowed)
__device__ float g_style[BATCH * CIN];    // modulated style s[b][ci]
__device__ float g_dcoef[BATCH * COUT];   // demod coefficient per (b,co)
__device__ float g_wsq[COUT * CIN];       // sum_k conv_weight[co,ci,k]^2

// ---------------------------------------------------------------------------
// Kernel 0: wsq[co,ci] = sum over 3x3 taps of conv_weight^2
// ---------------------------------------------------------------------------
__global__ void wsq_kernel(const float* __restrict__ cw) {
    int idx = blockIdx.x * blockDim.x + threadIdx.x;
    if (idx < COUT * CIN) {
        const float* p = cw + (size_t)idx * 9;
        float s = 0.f;
#pragma unroll
        for (int k = 0; k < 9; k++) { float v = p[k]; s += v * v; }
        g_wsq[idx] = s;
    }
}

// ---------------------------------------------------------------------------
// Kernel 1: style[b,ci] = (w_latent[b] . affine_weight[ci]) / sqrt(512) + bias
// ---------------------------------------------------------------------------
__global__ void style_kernel(const float* __restrict__ wl,
                             const float* __restrict__ aw,
                             const float* __restrict__ ab) {
    int b = blockIdx.x;
    int ci = threadIdx.x;
    __shared__ float sw[WDIM];
    sw[ci] = wl[b * WDIM + ci];
    __syncthreads();
    const float* row = aw + (size_t)ci * WDIM;
    float acc = 0.f;
#pragma unroll 8
    for (int k = 0; k < WDIM; k++) acc += sw[k] * row[k];
    g_style[b * CIN + ci] = acc * 0.04419417382415922f + ab[ci];  // 1/sqrt(512)
}

// ---------------------------------------------------------------------------
// Kernel 2: dcoef[b,co] = rsqrt( sum_ci style[b,ci]^2 * wsq[co,ci] + 1e-8 )
// ---------------------------------------------------------------------------
__global__ void dcoef_kernel() {
    int b = blockIdx.x;
    int co = threadIdx.x;  // also spans ci (CIN == COUT == 512)
    __shared__ float s2[CIN];
    float st = g_style[b * CIN + co];
    s2[co] = st * st;
    __syncthreads();
    const float* row = g_wsq + (size_t)co * CIN;
    float acc = 0.f;
#pragma unroll 8
    for (int ci = 0; ci < CIN; ci++) acc += s2[ci] * row[ci];
    g_dcoef[b * COUT + co] = rsqrtf(acc + 1e-8f);
}

// ---------------------------------------------------------------------------
// Kernel 3: main fused conv-transpose(stride 2) + FIR + noise/bias/lrelu/clamp
//
// Intermediate y is 65x65 per (b,co):
//   y[2m+s, 2n+t] accumulated per 2x2 "cell" (m,n) in [0,33)^2:
//     y[2m,2n]     = x[m,n]w00 + x[m,n-1]w02 + x[m-1,n]w20 + x[m-1,n-1]w22
//     y[2m,2n+1]   = x[m,n]w01 + x[m-1,n]w21
//     y[2m+1,2n]   = x[m,n]w10 + x[m,n-1]w12
//     y[2m+1,2n+1] = x[m,n]w11
//   (cells with 2m+s or 2n+t > 64 are dropped)
// FIR: out[u,v] = sum_{a,b in [0,4)} f[a]f[b]/16 * ypad[u+a][v+b],
//   ypad[i][j] = y[i-1][j-1], zero borders (incl. y[65] := 0).
// ---------------------------------------------------------------------------
__global__ __launch_bounds__(256) void conv_kernel(
    const float* __restrict__ x, const float* __restrict__ cw,
    const float* __restrict__ noise, const float* __restrict__ nstr,
    const float* __restrict__ bias, float* __restrict__ out) {
    const int co = blockIdx.x, b = blockIdx.y;
    const int tid = threadIdx.x;

    __shared__ float xp[34][36];  // x padded by 1 (zeros at border), row stride 36
    __shared__ float yp[67][68];  // ypad, zero borders

    for (int i = tid; i < 34 * 36; i += 256) ((float*)xp)[i] = 0.f;
    for (int i = tid; i < 67 * 68; i += 256) ((float*)yp)[i] = 0.f;

    // Cell assignment: cell id = tid + 256*i, i in [0,5); 33*33 = 1089 cells.
    // Slots 0..3 always valid (max id 1023); slot 4 valid iff tid < 65.
    float acc[5][4];
#pragma unroll
    for (int i = 0; i < 5; i++)
#pragma unroll
        for (int j = 0; j < 4; j++) acc[i][j] = 0.f;

    int cm[5], cn[5];
#pragma unroll
    for (int i = 0; i < 5; i++) {
        int c = tid + 256 * i;
        cm[i] = c / 33;
        cn[i] = c % 33;
    }
    const bool v4 = (tid + 1024) < 1089;

    const float* xb  = x + (size_t)b * CIN * (HH * HH);
    const float* cwc = cw + (size_t)co * CIN * 9;
    const float* stb = g_style + b * CIN;

    __syncthreads();

    for (int ci = 0; ci < CIN; ci++) {
        // cooperative load of 32x32 x tile into padded smem (4 floats/thread)
        float4 xv = ((const float4*)(xb + ci * 1024))[tid];
        int e = tid * 4;
        int r = (e >> 5) + 1;
        int c0 = (e & 31) + 1;
        xp[r][c0] = xv.x; xp[r][c0 + 1] = xv.y;
        xp[r][c0 + 2] = xv.z; xp[r][c0 + 3] = xv.w;
        __syncthreads();

        float s = stb[ci];
        float w[9];
#pragma unroll
        for (int k = 0; k < 9; k++) w[k] = cwc[ci * 9 + k] * s;

#pragma unroll
        for (int i = 0; i < 5; i++) {
            if (i == 4 && !v4) break;
            const float* p = &xp[cm[i]][cn[i]];
            float a00 = p[0], a01 = p[1], a10 = p[36], a11 = p[37];
            // a11 = x[m,n], a10 = x[m,n-1], a01 = x[m-1,n], a00 = x[m-1,n-1]
            acc[i][0] += a11 * w[0];
            acc[i][0] += a10 * w[2];
            acc[i][0] += a01 * w[6];
            acc[i][0] += a00 * w[8];
            acc[i][1] += a11 * w[1];
            acc[i][1] += a01 * w[7];
            acc[i][2] += a11 * w[3];
            acc[i][2] += a10 * w[5];
            acc[i][3] += a11 * w[4];
        }
        __syncthreads();
    }

    // write cells into padded y with demod scaling
    const float dc = g_dcoef[b * COUT + co];
#pragma unroll
    for (int i = 0; i < 5; i++) {
        if (i == 4 && !v4) break;
        int m = cm[i], n = cn[i];
        yp[2 * m + 1][2 * n + 1] = acc[i][0] * dc;
        if (n < 32) yp[2 * m + 1][2 * n + 2] = acc[i][1] * dc;
        if (m < 32) yp[2 * m + 2][2 * n + 1] = acc[i][2] * dc;
        if (m < 32 && n < 32) yp[2 * m + 2][2 * n + 2] = acc[i][3] * dc;
    }
    __syncthreads();

    // FIR (separable [1,3,3,1]/4 each dim) + noise + bias + lrelu + clamp
    const float nst = nstr[0];
    const float bc = bias[co];
    const float* nzb = noise + (size_t)b * 4096;
    float* ob = out + (((size_t)b * COUT + co) << 12);
    const float fw0 = 0.25f, fw1 = 0.75f;

#pragma unroll 4
    for (int j = 0; j < 16; j++) {
        int px = tid + 256 * j;
        int u = px >> 6, v = px & 63;
        float sum = 0.f;
#pragma unroll
        for (int a = 0; a < 4; a++) {
            float fa = (a == 0 || a == 3) ? fw0 : fw1;
            float rs = fw0 * yp[u + a][v] + fw1 * yp[u + a][v + 1] +
                       fw1 * yp[u + a][v + 2] + fw0 * yp[u + a][v + 3];
            sum += fa * rs;
        }
        float val = sum + nzb[px] * nst + bc;
        val = (val > 0.f) ? val : 0.2f * val;   // leaky_relu 0.2
        val *= 1.4142135623730951f;             // gain sqrt(2)
        val = fminf(fmaxf(val, -256.f), 256.f); // clamp
        ob[px] = val;
    }
}

// ---------------------------------------------------------------------------
// Launch
// inputs: 0:x 1:w_latent 2:affine_weight 3:affine_bias 4:conv_weight
//         5:noise 6:noise_strength 7:bias
// ---------------------------------------------------------------------------
extern "C" void kernel_launch(void* const* d_in, const int* in_sizes, int n_in,
                              void* d_out, int out_size) {
    const float* x  = (const float*)d_in[0];
    const float* wl = (const float*)d_in[1];
    const float* aw = (const float*)d_in[2];
    const float* ab = (const float*)d_in[3];
    const float* cw = (const float*)d_in[4];
    const float* nz = (const float*)d_in[5];
    const float* ns = (const float*)d_in[6];
    const float* bs = (const float*)d_in[7];
    float* out = (float*)d_out;

    wsq_kernel<<<(COUT * CIN + 255) / 256, 256>>>(cw);
    style_kernel<<<BATCH, 512>>>(wl, aw, ab);
    dcoef_kernel<<<BATCH, 512>>>();

    dim3 grid(COUT, BATCH);  // co fastest -> blocks sharing x[b] co-resident in L2
    conv_kernel<<<grid, 256>>>(x, cw, nz, ns, bs, out);
}

// round 6
// speedup vs baseline: 7.1467x; 7.1467x over previous
#include <cuda_runtime.h>
#include <cstdint>
#include <math.h>

#define BATCH 16
#define CIN 512
#define COUT 512
#define WDIM 512
#define MTOT 4608      // 9 * 512
#define NTOT 16384     // 16 * 1024

// ------------------------- static scratch (no allocs) -----------------------
__device__ float g_style[BATCH * CIN];
__device__ float g_dcoef[BATCH * COUT];
__device__ float g_wsq[COUT * CIN];
__device__ float g_A[MTOT * 512];          // A[(k*512+co)][ci], tf32-rounded
__device__ float g_B[NTOT * 512];          // B[(b*1024+p)][ci], tf32-rounded
__device__ float g_z[(size_t)MTOT * NTOT]; // z[(k,co)][(b,p)] fp32

// ------------------------------ helpers -------------------------------------
static __device__ __forceinline__ uint32_t smem_u32(const void* p) {
    uint32_t a;
    asm("{ .reg .u64 t; cvta.to.shared.u64 t, %1; cvt.u32.u64 %0, t; }"
        : "=r"(a) : "l"(p));
    return a;
}
static __device__ __forceinline__ float to_tf32(float v) {
    uint32_t t;
    asm("cvt.rna.tf32.f32 %0, %1;" : "=r"(t) : "f"(v));
    return __uint_as_float(t);
}

// ---------------------------------------------------------------------------
// prep kernels
// ---------------------------------------------------------------------------
__global__ void wsq_kernel(const float* __restrict__ cw) {
    int idx = blockIdx.x * blockDim.x + threadIdx.x;
    if (idx < COUT * CIN) {
        const float* p = cw + (size_t)idx * 9;
        float s = 0.f;
#pragma unroll
        for (int k = 0; k < 9; k++) { float v = p[k]; s += v * v; }
        g_wsq[idx] = s;
    }
}

__global__ void style_kernel(const float* __restrict__ wl,
                             const float* __restrict__ aw,
                             const float* __restrict__ ab) {
    int b = blockIdx.x, ci = threadIdx.x;
    __shared__ float sw[WDIM];
    sw[ci] = wl[b * WDIM + ci];
    __syncthreads();
    const float* row = aw + (size_t)ci * WDIM;
    float acc = 0.f;
#pragma unroll 8
    for (int k = 0; k < WDIM; k++) acc += sw[k] * row[k];
    g_style[b * CIN + ci] = acc * 0.04419417382415922f + ab[ci];
}

__global__ void dcoef_kernel() {
    int b = blockIdx.x, co = threadIdx.x;
    __shared__ float s2[CIN];
    float st = g_style[b * CIN + co];
    s2[co] = st * st;
    __syncthreads();
    const float* row = g_wsq + (size_t)co * CIN;
    float acc = 0.f;
#pragma unroll 8
    for (int ci = 0; ci < CIN; ci++) acc += s2[ci] * row[ci];
    g_dcoef[b * COUT + co] = rsqrtf(acc + 1e-8f);
}

// A[(k*512+co)][ci] = cw[co][ci][k]  (tf32-rounded)
__global__ void apack_kernel(const float* __restrict__ cw) {
    int idx = blockIdx.x * blockDim.x + threadIdx.x;
    if (idx < MTOT * 512) {
        int ci = idx & 511;
        int m = idx >> 9;
        int co = m & 511;
        int k = m >> 9;
        g_A[idx] = to_tf32(cw[((size_t)co * 512 + ci) * 9 + k]);
    }
}

// B[(b*1024+p)][ci] = x[b][ci][p] * style[b][ci]   (32x128 smem transpose)
__global__ __launch_bounds__(256) void btpack_kernel(const float* __restrict__ x) {
    const int ct = blockIdx.x;  // ci tile (16 of 32)
    const int pt = blockIdx.y;  // p tile (8 of 128)
    const int b = blockIdx.z;
    __shared__ float sm[32][129];
    const int tid = threadIdx.x;
    const int pl = tid & 127, c0 = tid >> 7;
    const float* xb = x + ((size_t)b * 512 + ct * 32) * 1024 + pt * 128;
    const float* stb = g_style + b * 512 + ct * 32;
#pragma unroll
    for (int cl = c0; cl < 32; cl += 2)
        sm[cl][pl] = xb[(size_t)cl * 1024 + pl] * stb[cl];
    __syncthreads();
    const int cl2 = tid & 31, p2b = tid >> 5;
    float* ob = g_B + ((size_t)b * 1024 + pt * 128) * 512 + ct * 32;
#pragma unroll
    for (int pp = p2b; pp < 128; pp += 8)
        ob[(size_t)pp * 512 + cl2] = to_tf32(sm[cl2][pp]);
}

// ---------------------------------------------------------------------------
// GEMM via mma.sync tf32 (sm_80-class path; tcgen05 blocked by ptxas target).
// z[m][n] = sum_ci A[m][ci] * B[n][ci].
// CTA tile 128x128, BK=16, double-buffered cp.async.
// 8 warps as 2(M) x 4(N); warp tile 64x32; mma m16n8k8.
// smem rows padded to 20 floats (80B) -> conflict-free LDSM.
// ---------------------------------------------------------------------------
#define BK 16
#define LDP 20  // padded row length in floats

__global__ __launch_bounds__(256) void gemm_kernel() {
    __shared__ float As[2][128 * LDP];
    __shared__ float Bs[2][128 * LDP];

    const int tid = threadIdx.x;
    const int wid = tid >> 5, lane = tid & 31;
    const int n0g = blockIdx.x * 128, m0g = blockIdx.y * 128;
    const int wm = wid & 1, wn = wid >> 1;
    const int m0w = wm * 64, n0w = wn * 32;

    const float* Ag = g_A + (size_t)m0g * 512;
    const float* Bg = g_B + (size_t)n0g * 512;

    const uint32_t sA0 = smem_u32(&As[0][0]);
    const uint32_t sB0 = smem_u32(&Bs[0][0]);
    const uint32_t bufstride = 128 * LDP * 4;

    // cp.async tile fill: 512 16B chunks per operand, 2 per thread
    const int lrow = tid >> 2;       // 0..63 base row
    const int lch = tid & 3;         // 16B chunk in row

#define ISSUE_STAGE(st, buf) do {                                              \
    int kb = (st) * BK;                                                        \
    _Pragma("unroll")                                                          \
    for (int i = 0; i < 2; i++) {                                              \
        int r = lrow + i * 64;                                                 \
        uint32_t doff = (uint32_t)(r * LDP + lch * 4) * 4 + (buf) * bufstride; \
        asm volatile("cp.async.cg.shared.global [%0], [%1], 16;"               \
                     :: "r"(sA0 + doff), "l"(Ag + (size_t)r * 512 + kb + lch * 4) : "memory"); \
        asm volatile("cp.async.cg.shared.global [%0], [%1], 16;"               \
                     :: "r"(sB0 + doff), "l"(Bg + (size_t)r * 512 + kb + lch * 4) : "memory"); \
    }                                                                          \
    asm volatile("cp.async.commit_group;" ::: "memory");                       \
} while (0)

    float acc[4][4][4];
#pragma unroll
    for (int a = 0; a < 4; a++)
#pragma unroll
        for (int b = 0; b < 4; b++)
#pragma unroll
            for (int c = 0; c < 4; c++) acc[a][b][c] = 0.f;

    // ldmatrix lane-derived offsets
    const int arow_off = ((lane >> 3) & 1) * 8 + (lane & 7);  // quadrant row
    const int acol_off = ((lane >> 4) & 1) * 4;               // quadrant k-col
    const int brow = lane & 7;
    const int bcol_off = ((lane >> 3) & 1) * 4;

    ISSUE_STAGE(0, 0);
    ISSUE_STAGE(1, 1);

    const int NSTAGE = 512 / BK;  // 32
#pragma unroll 1
    for (int kt = 0; kt < NSTAGE; kt++) {
        const int buf = kt & 1;
        if (kt == NSTAGE - 1)
            asm volatile("cp.async.wait_group 0;" ::: "memory");
        else
            asm volatile("cp.async.wait_group 1;" ::: "memory");
        __syncthreads();

        const uint32_t smA = sA0 + buf * bufstride;
        const uint32_t smB = sB0 + buf * bufstride;

#pragma unroll
        for (int s = 0; s < 2; s++) {
            const int k0 = s * 8;
            uint32_t a[4][4];
            uint32_t b[4][2];
#pragma unroll
            for (int mf = 0; mf < 4; mf++) {
                uint32_t addr = smA +
                    (uint32_t)((m0w + mf * 16 + arow_off) * LDP + k0 + acol_off) * 4;
                asm volatile(
                    "ldmatrix.sync.aligned.m8n8.x4.shared.b16 {%0,%1,%2,%3}, [%4];"
                    : "=r"(a[mf][0]), "=r"(a[mf][1]), "=r"(a[mf][2]), "=r"(a[mf][3])
                    : "r"(addr));
            }
#pragma unroll
            for (int nf = 0; nf < 4; nf++) {
                uint32_t addr = smB +
                    (uint32_t)((n0w + nf * 8 + brow) * LDP + k0 + bcol_off) * 4;
                asm volatile(
                    "ldmatrix.sync.aligned.m8n8.x2.shared.b16 {%0,%1}, [%2];"
                    : "=r"(b[nf][0]), "=r"(b[nf][1])
                    : "r"(addr));
            }
#pragma unroll
            for (int mf = 0; mf < 4; mf++)
#pragma unroll
                for (int nf = 0; nf < 4; nf++) {
                    asm volatile(
                        "mma.sync.aligned.m16n8k8.row.col.f32.tf32.tf32.f32 "
                        "{%0,%1,%2,%3}, {%4,%5,%6,%7}, {%8,%9}, {%0,%1,%2,%3};"
                        : "+f"(acc[mf][nf][0]), "+f"(acc[mf][nf][1]),
                          "+f"(acc[mf][nf][2]), "+f"(acc[mf][nf][3])
                        : "r"(a[mf][0]), "r"(a[mf][1]), "r"(a[mf][2]), "r"(a[mf][3]),
                          "r"(b[nf][0]), "r"(b[nf][1]));
                }
        }
        __syncthreads();
        if (kt + 2 < NSTAGE) ISSUE_STAGE(kt + 2, buf);
    }

    // epilogue: store accumulators to g_z (float2 per half-frag)
    float* zbase = g_z + (size_t)(m0g + m0w) * NTOT + (n0g + n0w);
    const int rq = lane >> 2, cq = lane & 3;
#pragma unroll
    for (int mf = 0; mf < 4; mf++)
#pragma unroll
        for (int nf = 0; nf < 4; nf++) {
            float* p0 = zbase + (size_t)(mf * 16 + rq) * NTOT + nf * 8 + 2 * cq;
            *(float2*)p0 = make_float2(acc[mf][nf][0], acc[mf][nf][1]);
            float* p1 = p0 + (size_t)8 * NTOT;
            *(float2*)p1 = make_float2(acc[mf][nf][2], acc[mf][nf][3]);
        }
}

// ---------------------------------------------------------------------------
// assemble: scatter 9 z planes -> y (65x65), demod, FIR, noise/bias/act/clamp
// y[2i+ky][2j+kx] += z_{ky*3+kx}[i][j];  ypad[r][c] = y[r-1][c-1]
// ---------------------------------------------------------------------------
__global__ __launch_bounds__(256) void assemble_kernel(
    const float* __restrict__ noise, const float* __restrict__ nstr,
    const float* __restrict__ bias, float* __restrict__ out) {
    const int co = blockIdx.x, b = blockIdx.y;
    const int tid = threadIdx.x;
    __shared__ float yp[67][68];
    for (int i = tid; i < 67 * 68; i += 256) ((float*)yp)[i] = 0.f;
    __syncthreads();

#pragma unroll 1
    for (int k = 0; k < 9; k++) {
        const float* zp = g_z + ((size_t)(k * 512 + co)) * NTOT + b * 1024;
        float4 v = ((const float4*)zp)[tid];
        int p = tid * 4;
        int i = p >> 5, j = p & 31;
        int row = 2 * i + 1 + k / 3;
        int col = 2 * j + 1 + (k % 3);
        yp[row][col] += v.x;
        yp[row][col + 2] += v.y;
        yp[row][col + 4] += v.z;
        yp[row][col + 6] += v.w;
        __syncthreads();
    }

    const float dc = g_dcoef[b * COUT + co];
    const float nst = nstr[0];
    const float bc = bias[co];
    const float* nzb = noise + (size_t)b * 4096;
    float* ob = out + (((size_t)b * COUT + co) << 12);
    const float fw0 = 0.25f, fw1 = 0.75f;

#pragma unroll 4
    for (int jj = 0; jj < 16; jj++) {
        int px = tid + 256 * jj;
        int u = px >> 6, v = px & 63;
        float sum = 0.f;
#pragma unroll
        for (int a = 0; a < 4; a++) {
            float fa = (a == 0 || a == 3) ? fw0 : fw1;
            float rs = fw0 * yp[u + a][v] + fw1 * yp[u + a][v + 1] +
                       fw1 * yp[u + a][v + 2] + fw0 * yp[u + a][v + 3];
            sum += fa * rs;
        }
        float val = sum * dc + nzb[px] * nst + bc;
        val = (val > 0.f) ? val : 0.2f * val;
        val *= 1.4142135623730951f;
        val = fminf(fmaxf(val, -256.f), 256.f);
        ob[px] = val;
    }
}

// ---------------------------------------------------------------------------
// launch: 0:x 1:w_latent 2:affine_weight 3:affine_bias 4:conv_weight
//         5:noise 6:noise_strength 7:bias
// ---------------------------------------------------------------------------
extern "C" void kernel_launch(void* const* d_in, const int* in_sizes, int n_in,
                              void* d_out, int out_size) {
    const float* x = (const float*)d_in[0];
    const float* wl = (const float*)d_in[1];
    const float* aw = (const float*)d_in[2];
    const float* ab = (const float*)d_in[3];
    const float* cw = (const float*)d_in[4];
    const float* nz = (const float*)d_in[5];
    const float* ns = (const float*)d_in[6];
    const float* bs = (const float*)d_in[7];
    float* out = (float*)d_out;

    wsq_kernel<<<(COUT * CIN + 255) / 256, 256>>>(cw);
    style_kernel<<<BATCH, 512>>>(wl, aw, ab);
    dcoef_kernel<<<BATCH, 512>>>();
    apack_kernel<<<(MTOT * 512 + 255) / 256, 256>>>(cw);
    btpack_kernel<<<dim3(16, 8, BATCH), 256>>>(x);
    gemm_kernel<<<dim3(NTOT / 128, MTOT / 128), 256>>>();
    assemble_kernel<<<dim3(COUT, BATCH), 256>>>(nz, ns, bs, out);
}